// round 12
// baseline (speedup 1.0000x reference)
#include <cuda_runtime.h>
#include <math.h>

// ---------------------------------------------------------------------------
// Problem constants (fixed by setup_inputs)
// ---------------------------------------------------------------------------
#define R_ROIS  256
#define C_CH    256
#define POOL    7
#define KDIM    (C_CH * POOL * POOL)   // 12544
#define NH1     1024
#define NCLSLOC 84
#define NSCORE  21

// ---------------------------------------------------------------------------
// Scratch (device globals; no allocation allowed)
// ---------------------------------------------------------------------------
__device__ float g_pooled[R_ROIS * KDIM];   // [r][c*49 + ph*7 + pw]
__device__ float g_h1[R_ROIS * NH1];
__device__ float g_h2[R_ROIS * NH1];

// ---------------------------------------------------------------------------
// RoI max-pool, torchvision RoIPool semantics + MB=6 sample cap, multi-level.
// One block per roi, one thread per channel.
//
// KEY CHANGE (R11): roi/7 is computed as roi * fl32(1/7) — reciprocal
// multiply — to match XLA's lowering of division-by-constant. fl32(1/7) is
// ~4.5e-8 ABOVE 1/7, so for roi_h = 7q (q in lower binade half) the product
// rounds UP to q+ulp, making every ceil((p+1)*rh7) one larger than the IEEE-
// division result. IEEE division here (all prior rounds) systematically
// diverges from such a reference on ~1/7 of rois per axis.
// ---------------------------------------------------------------------------
__global__ void __launch_bounds__(C_CH) pool_kernel(
    const float* __restrict__ f2, const float* __restrict__ f3,
    const float* __restrict__ f4, const float* __restrict__ f5,
    const float* __restrict__ rois, const int* __restrict__ ridx,
    const int* __restrict__ img_h_p, float* __restrict__ pooled)
{
    const int r = blockIdx.x;
    const int c = threadIdx.x;

    float y1 = rois[r * 4 + 0], x1 = rois[r * 4 + 1];
    float y2 = rois[r * 4 + 2], x2 = rois[r * 4 + 3];

    float hh  = __fadd_rn(__fsub_rn(y2, y1), 1.0f);
    float wwf = __fadd_rn(__fsub_rn(x2, x1), 1.0f);
    float area = __fmul_rn(hh, wwf);
    float s    = __fsqrt_rn(area);
    float xarg = __fdiv_rn(s, 224.0f);
    float vlog = (float)log((double)xarg);      // correctly-rounded fp32 log
    float v    = __fadd_rn(vlog, 4.0f);
    float lv   = rintf(v);                      // round half-even
    lv = fminf(fmaxf(lv, 2.0f), 5.0f);
    int lvl = (int)lv;

    const float* feat; int H;
    if      (lvl == 2) { feat = f2; H = 200; }
    else if (lvl == 3) { feat = f3; H = 100; }
    else if (lvl == 4) { feat = f4; H = 50;  }
    else               { feat = f5; H = 25;  }
    const int W = H;

    float imgh  = img_h_p ? (float)(*img_h_p) : 800.0f;
    float scale = __fdiv_rn((float)H, imgh);    // exact power of two

    int rsw = (int)rintf(__fmul_rn(x1, scale));
    int rsh = (int)rintf(__fmul_rn(y1, scale));
    int rew = (int)rintf(__fmul_rn(x2, scale));
    int reh = (int)rintf(__fmul_rn(y2, scale));
    float roi_w = fmaxf((float)(rew - rsw + 1), 1.0f);
    float roi_h = fmaxf((float)(reh - rsh + 1), 1.0f);

    // === THE R11 CHANGE: reciprocal multiply, matching XLA div-by-const ===
    const float INV7 = 1.0f / 7.0f;             // fl32(1/7), compile-time
    float rw7 = __fmul_rn(roi_w, INV7);
    float rh7 = __fmul_rn(roi_h, INV7);

    int hs[POOL], he[POOL], ws[POOL], we[POOL];
    #pragma unroll
    for (int p = 0; p < POOL; p++) {
        hs[p] = min(max((int)floorf(__fmul_rn((float)p,       rh7)) + rsh, 0), H);
        he[p] = min(max((int)ceilf (__fmul_rn((float)(p + 1), rh7)) + rsh, 0), H);
        ws[p] = min(max((int)floorf(__fmul_rn((float)p,       rw7)) + rsw, 0), W);
        we[p] = min(max((int)ceilf (__fmul_rn((float)(p + 1), rw7)) + rsw, 0), W);
    }

    const float* fb = feat + (size_t)(ridx[r] * C_CH + c) * H * W;
    float* outp = pooled + (size_t)r * KDIM + c * (POOL * POOL);

    #pragma unroll
    for (int ph = 0; ph < POOL; ph++) {
        int ys  = hs[ph];
        int yeF = he[ph];
        int ye  = min(yeF, ys + 6);      // MB = 6 offsets (0..5)
        #pragma unroll
        for (int pw = 0; pw < POOL; pw++) {
            int xs  = ws[pw];
            int xeF = we[pw];
            int xe  = min(xeF, xs + 6);
            float best;
            if (yeF <= ys || xeF <= xs) {
                best = 0.0f;             // empty bin (pre-cap test)
            } else {
                best = -INFINITY;
                for (int y = ys; y < ye; y++) {
                    const float* rowp = fb + (size_t)y * W;
                    for (int x = xs; x < xe; x++)
                        best = fmaxf(best, rowp[x]);
                }
            }
            outp[ph * POOL + pw] = best;
        }
    }
}

// ---------------------------------------------------------------------------
// C[M][N] = relu?( A[M][K] * B[N][K]^T + bias[N] )   (fp32 SIMT, 64x64 tile)
// ---------------------------------------------------------------------------
__global__ void __launch_bounds__(256) gemm_bias_relu(
    const float* __restrict__ A, const float* __restrict__ B,
    const float* __restrict__ bias, float* __restrict__ C,
    int M, int N, int K, int do_relu)
{
    __shared__ float As[16][68];
    __shared__ float Bs[16][68];

    const int t  = threadIdx.x;
    const int m0 = blockIdx.y * 64;
    const int n0 = blockIdx.x * 64;

    const int arow = t >> 2;
    const int ac4  = (t & 3) << 2;
    const float* Ag = A + (size_t)(m0 + arow) * K + ac4;
    const float* Bg = B + (size_t)(n0 + arow) * K + ac4;

    float acc[4][4];
    #pragma unroll
    for (int i = 0; i < 4; i++)
        #pragma unroll
        for (int j = 0; j < 4; j++) acc[i][j] = 0.0f;

    const int tm = (t >> 4) << 2;
    const int tn = (t & 15) << 2;

    for (int kt = 0; kt < K; kt += 16) {
        float4 av = *(const float4*)(Ag + kt);
        float4 bv = *(const float4*)(Bg + kt);
        As[ac4 + 0][arow] = av.x; As[ac4 + 1][arow] = av.y;
        As[ac4 + 2][arow] = av.z; As[ac4 + 3][arow] = av.w;
        Bs[ac4 + 0][arow] = bv.x; Bs[ac4 + 1][arow] = bv.y;
        Bs[ac4 + 2][arow] = bv.z; Bs[ac4 + 3][arow] = bv.w;
        __syncthreads();

        #pragma unroll
        for (int kk = 0; kk < 16; kk++) {
            float4 a = *(const float4*)&As[kk][tm];
            float4 b = *(const float4*)&Bs[kk][tn];
            acc[0][0] += a.x * b.x; acc[0][1] += a.x * b.y; acc[0][2] += a.x * b.z; acc[0][3] += a.x * b.w;
            acc[1][0] += a.y * b.x; acc[1][1] += a.y * b.y; acc[1][2] += a.y * b.z; acc[1][3] += a.y * b.w;
            acc[2][0] += a.z * b.x; acc[2][1] += a.z * b.y; acc[2][2] += a.z * b.z; acc[2][3] += a.z * b.w;
            acc[3][0] += a.w * b.x; acc[3][1] += a.w * b.y; acc[3][2] += a.w * b.z; acc[3][3] += a.w * b.w;
        }
        __syncthreads();
    }

    #pragma unroll
    for (int i = 0; i < 4; i++) {
        #pragma unroll
        for (int j = 0; j < 4; j++) {
            float v = acc[i][j] + (bias ? bias[n0 + tn + j] : 0.0f);
            if (do_relu) v = fmaxf(v, 0.0f);
            C[(size_t)(m0 + tm + i) * N + (n0 + tn + j)] = v;
        }
    }
}

// ---------------------------------------------------------------------------
// Heads
// ---------------------------------------------------------------------------
__global__ void __launch_bounds__(128) heads_kernel(
    const float* __restrict__ h2,
    const float* __restrict__ clw, const float* __restrict__ clb,
    const float* __restrict__ scw, const float* __restrict__ scb,
    float* __restrict__ out, int out_size)
{
    __shared__ float hrow[NH1];
    const int r = blockIdx.x;
    const int t = threadIdx.x;
    const float4* src = (const float4*)(h2 + (size_t)r * NH1);
    float4* dst = (float4*)hrow;
    for (int i = t; i < NH1 / 4; i += 128) dst[i] = src[i];
    __syncthreads();

    const int wid  = t >> 5;
    const int lane = t & 31;
    for (int o = wid; o < NCLSLOC + NSCORE; o += 4) {
        const float* wrow;
        float bv;
        size_t didx;
        if (o < NCLSLOC) {
            wrow = clw + (size_t)o * NH1;
            bv   = clb[o];
            didx = (size_t)r * NCLSLOC + o;
        } else {
            int oo = o - NCLSLOC;
            wrow = scw + (size_t)oo * NH1;
            bv   = scb[oo];
            didx = (size_t)R_ROIS * NCLSLOC + (size_t)r * NSCORE + oo;
        }
        float s = 0.0f;
        for (int k = lane; k < NH1; k += 32) s += hrow[k] * wrow[k];
        #pragma unroll
        for (int off = 16; off > 0; off >>= 1)
            s += __shfl_down_sync(0xffffffffu, s, off);
        if (lane == 0 && didx < (size_t)out_size) out[didx] = s + bv;
    }
}

// ---------------------------------------------------------------------------
// Launch
// ---------------------------------------------------------------------------
extern "C" void kernel_launch(void* const* d_in, const int* in_sizes, int n_in,
                              void* d_out, int out_size)
{
    const float* f2   = (const float*)d_in[0];
    const float* f3   = (const float*)d_in[1];
    const float* f4   = (const float*)d_in[2];
    const float* f5   = (const float*)d_in[3];
    const float* rois = (const float*)d_in[4];
    const int*   ridx = (const int*)d_in[5];
    const float* w1   = (const float*)d_in[6];
    const float* b1   = (const float*)d_in[7];
    const float* w2   = (const float*)d_in[8];
    const float* b2   = (const float*)d_in[9];
    const float* clw  = (const float*)d_in[10];
    const float* clb  = (const float*)d_in[11];
    const float* scw  = (const float*)d_in[12];
    const float* scb  = (const float*)d_in[13];
    const int*   imgh = (n_in > 14) ? (const int*)d_in[14] : nullptr;
    float* out = (float*)d_out;

    float *pooled, *h1, *h2;
    cudaGetSymbolAddress((void**)&pooled, g_pooled);
    cudaGetSymbolAddress((void**)&h1,     g_h1);
    cudaGetSymbolAddress((void**)&h2,     g_h2);

    pool_kernel<<<R_ROIS, C_CH>>>(f2, f3, f4, f5, rois, ridx, imgh, pooled);

    gemm_bias_relu<<<dim3(NH1 / 64, R_ROIS / 64), 256>>>(pooled, w1, b1, h1,
                                                         R_ROIS, NH1, KDIM, 1);

    gemm_bias_relu<<<dim3(NH1 / 64, R_ROIS / 64), 256>>>(h1, w2, b2, h2,
                                                         R_ROIS, NH1, NH1, 1);

    heads_kernel<<<R_ROIS, 128>>>(h2, clw, clb, scw, scb, out, out_size);
}

// round 13
// speedup vs baseline: 2.2726x; 2.2726x over previous
#include <cuda_runtime.h>
#include <math.h>

// ---------------------------------------------------------------------------
// Problem constants (fixed by setup_inputs)
// ---------------------------------------------------------------------------
#define R_ROIS  256
#define C_CH    256
#define POOL    7
#define KDIM    (C_CH * POOL * POOL)   // 12544
#define NH1     1024
#define NCLSLOC 84
#define NSCORE  21
#define NHEADS  (NCLSLOC + NSCORE)     // 105

// ---------------------------------------------------------------------------
// Scratch (device globals; no allocation allowed)
// ---------------------------------------------------------------------------
__device__ float g_pooled[R_ROIS * KDIM];        // [r][c*49 + ph*7 + pw]
__device__ float g_part1[4 * R_ROIS * NH1];      // fc1 split-K partials
__device__ float g_h1[R_ROIS * NH1];
__device__ float g_part2[2 * R_ROIS * NH1];      // fc2 split-K partials
__device__ float g_h2[R_ROIS * NH1];

// ---------------------------------------------------------------------------
// RoI max-pool — VALIDATED in R12, do not change the math.
// (roi/7 via reciprocal multiply matches XLA's div-by-constant lowering.)
// ---------------------------------------------------------------------------
__global__ void __launch_bounds__(C_CH) pool_kernel(
    const float* __restrict__ f2, const float* __restrict__ f3,
    const float* __restrict__ f4, const float* __restrict__ f5,
    const float* __restrict__ rois, const int* __restrict__ ridx,
    const int* __restrict__ img_h_p, float* __restrict__ pooled)
{
    const int r = blockIdx.x;
    const int c = threadIdx.x;

    float y1 = rois[r * 4 + 0], x1 = rois[r * 4 + 1];
    float y2 = rois[r * 4 + 2], x2 = rois[r * 4 + 3];

    float hh  = __fadd_rn(__fsub_rn(y2, y1), 1.0f);
    float wwf = __fadd_rn(__fsub_rn(x2, x1), 1.0f);
    float area = __fmul_rn(hh, wwf);
    float s    = __fsqrt_rn(area);
    float xarg = __fdiv_rn(s, 224.0f);
    float vlog = (float)log((double)xarg);      // correctly-rounded fp32 log
    float v    = __fadd_rn(vlog, 4.0f);
    float lv   = rintf(v);                      // round half-even
    lv = fminf(fmaxf(lv, 2.0f), 5.0f);
    int lvl = (int)lv;

    const float* feat; int H;
    if      (lvl == 2) { feat = f2; H = 200; }
    else if (lvl == 3) { feat = f3; H = 100; }
    else if (lvl == 4) { feat = f4; H = 50;  }
    else               { feat = f5; H = 25;  }
    const int W = H;

    float imgh  = img_h_p ? (float)(*img_h_p) : 800.0f;
    float scale = __fdiv_rn((float)H, imgh);    // exact power of two

    int rsw = (int)rintf(__fmul_rn(x1, scale));
    int rsh = (int)rintf(__fmul_rn(y1, scale));
    int rew = (int)rintf(__fmul_rn(x2, scale));
    int reh = (int)rintf(__fmul_rn(y2, scale));
    float roi_w = fmaxf((float)(rew - rsw + 1), 1.0f);
    float roi_h = fmaxf((float)(reh - rsh + 1), 1.0f);

    // Reciprocal multiply (matches XLA div-by-const) — PROTECTED
    const float INV7 = 1.0f / 7.0f;
    float rw7 = __fmul_rn(roi_w, INV7);
    float rh7 = __fmul_rn(roi_h, INV7);

    int hs[POOL], he[POOL], ws[POOL], we[POOL];
    #pragma unroll
    for (int p = 0; p < POOL; p++) {
        hs[p] = min(max((int)floorf(__fmul_rn((float)p,       rh7)) + rsh, 0), H);
        he[p] = min(max((int)ceilf (__fmul_rn((float)(p + 1), rh7)) + rsh, 0), H);
        ws[p] = min(max((int)floorf(__fmul_rn((float)p,       rw7)) + rsw, 0), W);
        we[p] = min(max((int)ceilf (__fmul_rn((float)(p + 1), rw7)) + rsw, 0), W);
    }

    const float* fb = feat + (size_t)(ridx[r] * C_CH + c) * H * W;
    float* outp = pooled + (size_t)r * KDIM + c * (POOL * POOL);

    #pragma unroll
    for (int ph = 0; ph < POOL; ph++) {
        int ys  = hs[ph];
        int yeF = he[ph];
        int ye  = min(yeF, ys + 6);      // MB = 6 offsets
        #pragma unroll
        for (int pw = 0; pw < POOL; pw++) {
            int xs  = ws[pw];
            int xeF = we[pw];
            int xe  = min(xeF, xs + 6);
            float best;
            if (yeF <= ys || xeF <= xs) {
                best = 0.0f;
            } else {
                best = -INFINITY;
                for (int y = ys; y < ye; y++) {
                    const float* rowp = fb + (size_t)y * W;
                    for (int x = xs; x < xe; x++)
                        best = fmaxf(best, rowp[x]);
                }
            }
            outp[ph * POOL + pw] = best;
        }
    }
}

// ---------------------------------------------------------------------------
// Split-K GEMM partials: Cpart[z][M][N] = A[M][ks:ke] * B[N][ks:ke]^T
// grid (N/64, M/64, S); block 256; 4x4 per thread. kchunk % 16 == 0.
// (This partials+reduce path was validated in R1: bit-identical to fused.)
// ---------------------------------------------------------------------------
__global__ void __launch_bounds__(256) gemm_nt_splitk(
    const float* __restrict__ A, const float* __restrict__ B,
    float* __restrict__ Cpart, int M, int N, int K, int kchunk)
{
    __shared__ float As[16][68];
    __shared__ float Bs[16][68];

    const int t  = threadIdx.x;
    const int m0 = blockIdx.y * 64;
    const int n0 = blockIdx.x * 64;
    const int ks = blockIdx.z * kchunk;
    const int ke = ks + kchunk;

    const int arow = t >> 2;
    const int ac4  = (t & 3) << 2;
    const float* Ag = A + (size_t)(m0 + arow) * K + ac4;
    const float* Bg = B + (size_t)(n0 + arow) * K + ac4;

    float acc[4][4];
    #pragma unroll
    for (int i = 0; i < 4; i++)
        #pragma unroll
        for (int j = 0; j < 4; j++) acc[i][j] = 0.0f;

    const int tm = (t >> 4) << 2;
    const int tn = (t & 15) << 2;

    for (int kt = ks; kt < ke; kt += 16) {
        float4 av = *(const float4*)(Ag + kt);
        float4 bv = *(const float4*)(Bg + kt);
        As[ac4 + 0][arow] = av.x; As[ac4 + 1][arow] = av.y;
        As[ac4 + 2][arow] = av.z; As[ac4 + 3][arow] = av.w;
        Bs[ac4 + 0][arow] = bv.x; Bs[ac4 + 1][arow] = bv.y;
        Bs[ac4 + 2][arow] = bv.z; Bs[ac4 + 3][arow] = bv.w;
        __syncthreads();

        #pragma unroll
        for (int kk = 0; kk < 16; kk++) {
            float4 a = *(const float4*)&As[kk][tm];
            float4 b = *(const float4*)&Bs[kk][tn];
            acc[0][0] += a.x * b.x; acc[0][1] += a.x * b.y; acc[0][2] += a.x * b.z; acc[0][3] += a.x * b.w;
            acc[1][0] += a.y * b.x; acc[1][1] += a.y * b.y; acc[1][2] += a.y * b.z; acc[1][3] += a.y * b.w;
            acc[2][0] += a.z * b.x; acc[2][1] += a.z * b.y; acc[2][2] += a.z * b.z; acc[2][3] += a.z * b.w;
            acc[3][0] += a.w * b.x; acc[3][1] += a.w * b.y; acc[3][2] += a.w * b.z; acc[3][3] += a.w * b.w;
        }
        __syncthreads();
    }

    float* Cp = Cpart + (size_t)blockIdx.z * M * N;
    #pragma unroll
    for (int i = 0; i < 4; i++)
        #pragma unroll
        for (int j = 0; j < 4; j++)
            Cp[(size_t)(m0 + tm + i) * N + (n0 + tn + j)] = acc[i][j];
}

// ---------------------------------------------------------------------------
// out[i] = relu( sum_s part[s][i] + bias[i % N] )
// ---------------------------------------------------------------------------
__global__ void reduce_bias_relu(const float* __restrict__ part,
                                 const float* __restrict__ bias,
                                 float* __restrict__ out,
                                 int S, int MN, int N)
{
    int i = blockIdx.x * blockDim.x + threadIdx.x;
    if (i >= MN) return;
    float s = bias[i % N];
    for (int ss = 0; ss < S; ss++) s += part[(size_t)ss * MN + i];
    out[i] = fmaxf(s, 0.0f);
}

// ---------------------------------------------------------------------------
// Heads as one tiled GEMM over the combined [105 x 1024] weight matrix.
// grid ((105+63)/64=2, 256/64=4) = 8 CTAs. Weights read once. Ragged-edge
// guards; writes the concatenated output layout directly.
// ---------------------------------------------------------------------------
__global__ void __launch_bounds__(256) heads_gemm(
    const float* __restrict__ h2,
    const float* __restrict__ clw, const float* __restrict__ clb,
    const float* __restrict__ scw, const float* __restrict__ scb,
    float* __restrict__ out)
{
    __shared__ float As[16][68];
    __shared__ float Bs[16][68];

    const int t  = threadIdx.x;
    const int m0 = blockIdx.y * 64;
    const int n0 = blockIdx.x * 64;

    const int arow = t >> 2;
    const int ac4  = (t & 3) << 2;
    const float* Ag = h2 + (size_t)(m0 + arow) * NH1 + ac4;

    const int brow = n0 + arow;          // combined output row 0..127
    const float* Bg = nullptr;
    if      (brow < NCLSLOC) Bg = clw + (size_t)brow * NH1 + ac4;
    else if (brow < NHEADS)  Bg = scw + (size_t)(brow - NCLSLOC) * NH1 + ac4;

    float acc[4][4];
    #pragma unroll
    for (int i = 0; i < 4; i++)
        #pragma unroll
        for (int j = 0; j < 4; j++) acc[i][j] = 0.0f;

    const int tm = (t >> 4) << 2;
    const int tn = (t & 15) << 2;

    for (int kt = 0; kt < NH1; kt += 16) {
        float4 av = *(const float4*)(Ag + kt);
        float4 bv = Bg ? *(const float4*)(Bg + kt) : make_float4(0.f, 0.f, 0.f, 0.f);
        As[ac4 + 0][arow] = av.x; As[ac4 + 1][arow] = av.y;
        As[ac4 + 2][arow] = av.z; As[ac4 + 3][arow] = av.w;
        Bs[ac4 + 0][arow] = bv.x; Bs[ac4 + 1][arow] = bv.y;
        Bs[ac4 + 2][arow] = bv.z; Bs[ac4 + 3][arow] = bv.w;
        __syncthreads();

        #pragma unroll
        for (int kk = 0; kk < 16; kk++) {
            float4 a = *(const float4*)&As[kk][tm];
            float4 b = *(const float4*)&Bs[kk][tn];
            acc[0][0] += a.x * b.x; acc[0][1] += a.x * b.y; acc[0][2] += a.x * b.z; acc[0][3] += a.x * b.w;
            acc[1][0] += a.y * b.x; acc[1][1] += a.y * b.y; acc[1][2] += a.y * b.z; acc[1][3] += a.y * b.w;
            acc[2][0] += a.z * b.x; acc[2][1] += a.z * b.y; acc[2][2] += a.z * b.z; acc[2][3] += a.z * b.w;
            acc[3][0] += a.w * b.x; acc[3][1] += a.w * b.y; acc[3][2] += a.w * b.z; acc[3][3] += a.w * b.w;
        }
        __syncthreads();
    }

    #pragma unroll
    for (int i = 0; i < 4; i++) {
        const int r = m0 + tm + i;
        #pragma unroll
        for (int j = 0; j < 4; j++) {
            const int o = n0 + tn + j;
            if (o < NCLSLOC) {
                out[(size_t)r * NCLSLOC + o] = acc[i][j] + clb[o];
            } else if (o < NHEADS) {
                const int oo = o - NCLSLOC;
                out[(size_t)R_ROIS * NCLSLOC + (size_t)r * NSCORE + oo] =
                    acc[i][j] + scb[oo];
            }
        }
    }
}

// ---------------------------------------------------------------------------
// Launch
// ---------------------------------------------------------------------------
extern "C" void kernel_launch(void* const* d_in, const int* in_sizes, int n_in,
                              void* d_out, int out_size)
{
    const float* f2   = (const float*)d_in[0];
    const float* f3   = (const float*)d_in[1];
    const float* f4   = (const float*)d_in[2];
    const float* f5   = (const float*)d_in[3];
    const float* rois = (const float*)d_in[4];
    const int*   ridx = (const int*)d_in[5];
    const float* w1   = (const float*)d_in[6];
    const float* b1   = (const float*)d_in[7];
    const float* w2   = (const float*)d_in[8];
    const float* b2   = (const float*)d_in[9];
    const float* clw  = (const float*)d_in[10];
    const float* clb  = (const float*)d_in[11];
    const float* scw  = (const float*)d_in[12];
    const float* scb  = (const float*)d_in[13];
    const int*   imgh = (n_in > 14) ? (const int*)d_in[14] : nullptr;
    float* out = (float*)d_out;

    float *pooled, *part1, *h1, *part2, *h2;
    cudaGetSymbolAddress((void**)&pooled, g_pooled);
    cudaGetSymbolAddress((void**)&part1,  g_part1);
    cudaGetSymbolAddress((void**)&h1,     g_h1);
    cudaGetSymbolAddress((void**)&part2,  g_part2);
    cudaGetSymbolAddress((void**)&h2,     g_h2);

    // 1) RoI max-pool
    pool_kernel<<<R_ROIS, C_CH>>>(f2, f3, f4, f5, rois, ridx, imgh, pooled);

    // 2) fc1: split-K=4 -> 256 CTAs (full chip), then fused reduce+bias+relu
    gemm_nt_splitk<<<dim3(NH1 / 64, R_ROIS / 64, 4), 256>>>(
        pooled, w1, part1, R_ROIS, NH1, KDIM, KDIM / 4);
    reduce_bias_relu<<<(R_ROIS * NH1 + 255) / 256, 256>>>(
        part1, b1, h1, 4, R_ROIS * NH1, NH1);

    // 3) fc2: split-K=2 -> 128 CTAs
    gemm_nt_splitk<<<dim3(NH1 / 64, R_ROIS / 64, 2), 256>>>(
        h1, w2, part2, R_ROIS, NH1, NH1, NH1 / 2);
    reduce_bias_relu<<<(R_ROIS * NH1 + 255) / 256, 256>>>(
        part2, b2, h2, 2, R_ROIS * NH1, NH1);

    // 4) heads: one 8-CTA GEMM, weights read once
    heads_gemm<<<dim3(2, R_ROIS / 64), 256>>>(h2, clw, clb, scw, scb, out);
}